// round 17
// baseline (speedup 1.0000x reference)
#include <cuda_runtime.h>
#include <cuda_bf16.h>
#include <mma.h>
#include <cstdint>

using namespace nvcuda;

#define BSZ 8
#define HID 64
#define NV  1024
#define NT  64
#define BHW (BSZ * HID * NV)
#define NTHR 512

// bf16 hi/lo split state [buf][(b*64+hid)*NV + v]
__device__ __nv_bfloat16 g_hh[2][BHW];
__device__ __nv_bfloat16 g_hl[2][BHW];
__device__ __nv_bfloat16 g_gh[NV * NV];       // graph hi  [w][v]
__device__ __nv_bfloat16 g_gl[NV * NV];       // graph lo
__device__ __nv_bfloat16 g_whh_h[192 * 64];   // W_hh hi [gate][hid]
__device__ __nv_bfloat16 g_whh_l[192 * 64];
__device__ float g_xh[BSZ][NV];
__device__ float g_reprs[(size_t)NT * BHW];   // step-major staging for reprs
__device__ int   g_mask_mode;                 // 0=byte, 1=int32, 2=float32

// smem byte offsets. GEMM buffers: [64 rows][136 cols] bf16, k-chunk = 128.
#define LDT 136
#define TILE_B (64 * LDT * 2)                 // 17408
#define OFF_AH(b) ((b) * TILE_B)              // 0 .. 34816
#define OFF_AL(b) (34816 + (b) * TILE_B)      // 34816 .. 69632
#define OFF_BH(b) (69632 + (b) * TILE_B)      // 69632 .. 104448
#define OFF_BL(b) (104448 + (b) * TILE_B)     // 104448 .. 139264
// post-GEMM regions alias the dead GEMM buffers:
#define OFF_P(k) ((k) * 18432)                // 4 k-split partials, f32 [64][72]
#define OFF_HD   OFF_P(0)                     // reduced h_diff (in place)
#define OFF_HN   OFF_P(1)                     // h_new, after reduction
#define OFF_HDH  73728                        // bf16 [64][72]
#define OFF_HDL  82944                        // bf16 [64][72]
#define OFF_GD   92160                        // f32 [192][72] -> ends 147456
// non-aliased tail:
#define OFF_XG   147456     // f32 [64]
#define OFF_PART 147712     // f32 [1024]
#define OFF_SX   151808     // f32 [64]  x(t+1)
#define OFF_SMK  152064     // f32 [64]  mask(t+1) as 0/1
#define OFF_GW   152320     // f32 7 x [64]
#define OFF_SXH  154112     // f32 [1024] staged g_xh[b][:]
#define SMEM_TOTAL 158208

// ---------------------------------------------------------------------------
__device__ __forceinline__ void cp_async16(uint32_t s, const void* g) {
    asm volatile("cp.async.ca.shared.global [%0], [%1], 16;" :: "r"(s), "l"(g));
}
__device__ __forceinline__ void cp_commit() { asm volatile("cp.async.commit_group;"); }
__device__ __forceinline__ void cp_wait0()  { asm volatile("cp.async.wait_group 0;"); }
__device__ __forceinline__ void cp_wait1()  { asm volatile("cp.async.wait_group 1;"); }
__device__ __forceinline__ void stcs(float* p, float v) {
    asm volatile("st.global.cs.f32 [%0], %1;" :: "l"(p), "f"(v));
}
__device__ __forceinline__ float tanh_fast(float x) {
    float y;
    asm("tanh.approx.f32 %0, %1;" : "=f"(y) : "f"(x));
    return y;
}

// ---------------------------------------------------------------------------
__global__ void detect_mask_kernel(const unsigned int* __restrict__ m) {
    __shared__ int viol_i, viol_f;
    if (threadIdx.x == 0) { viol_i = 0; viol_f = 0; }
    __syncthreads();
    int li = 0, lf = 0;
    const int nwords = (BSZ * NV * NT) / 4;
    for (int i = threadIdx.x; i < nwords; i += blockDim.x) {
        unsigned int w = m[i];
        if (w > 1u) li = 1;
        if (w != 0u && w != 0x3F800000u) lf = 1;
    }
    if (li) atomicOr(&viol_i, 1);
    if (lf) atomicOr(&viol_f, 1);
    __syncthreads();
    if (threadIdx.x == 0)
        g_mask_mode = (!viol_f) ? 2 : ((!viol_i) ? 1 : 0);
}

// Merged one-time setup: graph split, W_hh split, h0 init.
__global__ void setup_kernel(const float* __restrict__ graph,
                             const float* __restrict__ W_hh,
                             const float* __restrict__ h0) {
    int i = blockIdx.x * blockDim.x + threadIdx.x;
    {
        float v = graph[i];
        __nv_bfloat16 hi = __float2bfloat16(v);
        g_gh[i] = hi;
        g_gl[i] = __float2bfloat16(v - __bfloat162float(hi));
    }
    if (i < 192 * 64) {
        float v = W_hh[i];
        __nv_bfloat16 hi = __float2bfloat16(v);
        g_whh_h[i] = hi;
        g_whh_l[i] = __float2bfloat16(v - __bfloat162float(hi));
    }
    if (i < BHW) {
        int v  = i & (NV - 1);
        int hh = (i >> 10) & 63;
        float val = h0[hh * NV + v];
        __nv_bfloat16 hi = __float2bfloat16(val);
        g_hh[0][i] = hi;
        g_hl[0][i] = __float2bfloat16(val - __bfloat162float(hi));
    }
}

// t=0 prep from h0 directly. Grid (4, 8), 256 threads.
__global__ void prep_kernel(
    const float* __restrict__ x, const unsigned char* __restrict__ mask_raw,
    const float* __restrict__ h0,
    const float* __restrict__ W_init, const float* __restrict__ b_init,
    float* __restrict__ out_preds)
{
    int b = blockIdx.y;
    int v = blockIdx.x * 256 + threadIdx.x;
    float d = 0.f;
    #pragma unroll 16
    for (int hh = 0; hh < HID; hh++) d += W_init[hh] * h0[hh * NV + v];
    d += b_init[0];
    int xi = (b * NV + v) * NT + 0;
    int mode = g_mask_mode;
    bool m;
    if (mode == 0)      m = mask_raw[xi] != 0;
    else if (mode == 1) m = ((const int*)mask_raw)[xi] != 0;
    else                m = ((const float*)mask_raw)[xi] != 0.f;
    g_xh[b][v] = m ? x[xi] : d;
    out_preds[xi] = d;
}

// Final transpose: scratch [t][bhw] -> out_reprs [bhw][t]. 8192 blocks, 256 thr.
__global__ void __launch_bounds__(256) transpose_reprs_kernel(float* __restrict__ out) {
    __shared__ float sm[64][65];
    const int bhw0 = blockIdx.x * 64;
    const int c  = threadIdx.x & 63;
    const int r4 = threadIdx.x >> 6;
    #pragma unroll
    for (int i = 0; i < 16; i++) {
        int tt = r4 + 4 * i;
        sm[tt][c] = g_reprs[(size_t)tt * BHW + bhw0 + c];
    }
    __syncthreads();
    #pragma unroll
    for (int i = 0; i < 16; i++) {
        int row = r4 + 4 * i;
        out[(size_t)(bhw0 + row) * NT + c] = sm[c][row];
    }
}

// ---------------------------------------------------------------------------
// Step kernel: grid (16 w-tiles, 8 batches), 512 threads (16 warps).
// k-chunk = 128; warp = (kq, mh, nh) -> 32m x 32n partial over 2 ks-substeps.
// ---------------------------------------------------------------------------
__global__ void __launch_bounds__(NTHR) step_tc_kernel(int t, int cur,
    const float* __restrict__ x, const unsigned char* __restrict__ mask_raw,
    const float* __restrict__ ind_graph,
    const float* __restrict__ W_init, const float* __restrict__ b_init,
    const float* __restrict__ W_out,  const float* __restrict__ b_out,
    const float* __restrict__ W_ih,
    const float* __restrict__ b_ih,   const float* __restrict__ b_hh,
    float* __restrict__ out_imps, float* __restrict__ out_preds)
{
    extern __shared__ __align__(32) char smem[];
    const uint32_t sbase = (uint32_t)__cvta_generic_to_shared(smem);

    const int tid  = threadIdx.x;
    const int wid  = tid >> 5;
    const int lane = tid & 31;
    const int wt   = blockIdx.x;
    const int b    = blockIdx.y;          // batch == m-tile
    const int w0   = wt * 64;
    const int m0   = b * 64;
    const int nxt  = cur ^ 1;

    float* hd   = (float*)(smem + OFF_HD);
    __nv_bfloat16* hdh = (__nv_bfloat16*)(smem + OFF_HDH);
    __nv_bfloat16* hdl = (__nv_bfloat16*)(smem + OFF_HDL);
    float* gd   = (float*)(smem + OFF_GD);
    float* hn   = (float*)(smem + OFF_HN);
    float* xg   = (float*)(smem + OFF_XG);
    float* part = (float*)(smem + OFF_PART);
    float* sx   = (float*)(smem + OFF_SX);
    float* smk  = (float*)(smem + OFF_SMK);
    float* gw   = (float*)(smem + OFF_GW);   // 7 x [64]
    float* sxh  = (float*)(smem + OFF_SXH);  // [1024]

    // fill(kt): cp.async 4 bf16 tiles, 64 rows x 128 cols, ld=136. 512 threads.
    auto fill = [&](int kt) {
        int buf = kt & 1;
        int v0  = kt * 128;
        const __nv_bfloat16* srcs[4] = {
            g_hh[cur] + (size_t)m0 * NV + v0,
            g_hl[cur] + (size_t)m0 * NV + v0,
            g_gh      + (size_t)w0 * NV + v0,
            g_gl      + (size_t)w0 * NV + v0 };
        const uint32_t dsts[4] = {
            sbase + OFF_AH(buf), sbase + OFF_AL(buf),
            sbase + OFF_BH(buf), sbase + OFF_BL(buf) };
        #pragma unroll
        for (int i = 0; i < 8; i++) {
            const int mat = i >> 1;
            int cc = (i & 1) * NTHR + tid;      // 0..1023 16B chunks per matrix
            int row = cc >> 4, kc = cc & 15;
            cp_async16(dsts[mat] + row * (LDT * 2) + kc * 16,
                       srcs[mat] + row * NV + kc * 8);
        }
        cp_commit();
    };

    fill(0);

    // ---- stage g_xh[b][:] into smem (coalesced float4) ----
    if (tid < 256)
        ((float4*)sxh)[tid] = ((const float4*)&g_xh[b][0])[tid];

    // ---- stage gate weights/biases (per-hh) into smem ----
    if (tid >= 256 && tid < 320) {
        int h = tid - 256;
        gw[h]       = W_ih[h];                        // Wr
        gw[64 + h]  = W_ih[64 + h];                   // Wz
        gw[128 + h] = W_ih[128 + h];                  // Wn
        gw[192 + h] = b_ih[h] + b_hh[h];              // Br
        gw[256 + h] = b_ih[64 + h] + b_hh[64 + h];    // Bz
        gw[320 + h] = b_ih[128 + h];                  // Bn
        gw[384 + h] = b_hh[128 + h];                  // Bhn
    }

    // ---- prefetch x/mask for t+1 (overlapped) ----
    if (tid >= NTHR - 64 && t < NT - 1) {
        int w = tid - (NTHR - 64);
        int xi = (b * NV + w0 + w) * NT + (t + 1);
        int mode = g_mask_mode;
        bool m;
        if (mode == 0)      m = mask_raw[xi] != 0;
        else if (mode == 1) m = ((const int*)mask_raw)[xi] != 0;
        else                m = ((const float*)mask_raw)[xi] != 0.f;
        smk[w] = m ? 1.f : 0.f;
        sx[w]  = x[xi];
    }
    __syncthreads();   // sxh staged

    // ---- x_g: warp owns 4 rows; lanes stride within row (coalesced) ----
    {
        float4 xv[8];
        #pragma unroll
        for (int j = 0; j < 8; j++) xv[j] = ((const float4*)sxh)[j * 32 + lane];
        const int row0 = wid * 4;
        #pragma unroll
        for (int rr = 0; rr < 4; rr++) {
            const float4* ig = (const float4*)&ind_graph[(size_t)(w0 + row0 + rr) * NV];
            float s = 0.f;
            #pragma unroll
            for (int j = 0; j < 8; j++) {
                float4 a = ig[j * 32 + lane];
                s += a.x * xv[j].x + a.y * xv[j].y + a.z * xv[j].z + a.w * xv[j].w;
            }
            s += __shfl_xor_sync(0xffffffffu, s, 16);
            s += __shfl_xor_sync(0xffffffffu, s, 8);
            s += __shfl_xor_sync(0xffffffffu, s, 4);
            s += __shfl_xor_sync(0xffffffffu, s, 2);
            s += __shfl_xor_sync(0xffffffffu, s, 1);
            if (lane == 0) xg[row0 + rr] = s;
        }
    }

    // ---- GEMM, k-split: warp (kq = wid>>2, mh = (wid>>1)&1, nh = wid&1)
    //      computes 32m x 32n partial over ks = 2*kq .. 2*kq+1 per k-chunk.
    wmma::fragment<wmma::accumulator, 16, 16, 16, float> acc[2][2];
    #pragma unroll
    for (int mi = 0; mi < 2; mi++)
        #pragma unroll
        for (int ni = 0; ni < 2; ni++) wmma::fill_fragment(acc[mi][ni], 0.f);
    const int kq = wid >> 2, mh = (wid >> 1) & 1, nh = wid & 1;

    for (int kt = 0; kt < 8; kt++) {
        if (kt < 7) { fill(kt + 1); cp_wait1(); } else { cp_wait0(); }
        __syncthreads();                         // buffer kt ready
        const int buf = kt & 1;
        const __nv_bfloat16* Ah = (const __nv_bfloat16*)(smem + OFF_AH(buf));
        const __nv_bfloat16* Al = (const __nv_bfloat16*)(smem + OFF_AL(buf));
        const __nv_bfloat16* Bh = (const __nv_bfloat16*)(smem + OFF_BH(buf));
        const __nv_bfloat16* Bl = (const __nv_bfloat16*)(smem + OFF_BL(buf));
        #pragma unroll
        for (int kss = 0; kss < 2; kss++) {
            const int ks = kq * 2 + kss;
            wmma::fragment<wmma::matrix_a, 16, 16, 16, __nv_bfloat16, wmma::row_major> fah[2], fal[2];
            wmma::fragment<wmma::matrix_b, 16, 16, 16, __nv_bfloat16, wmma::col_major> fbh[2], fbl[2];
            #pragma unroll
            for (int mi = 0; mi < 2; mi++) {
                int aoff = (mh * 32 + mi * 16) * LDT + ks * 16;
                wmma::load_matrix_sync(fah[mi], Ah + aoff, LDT);
                wmma::load_matrix_sync(fal[mi], Al + aoff, LDT);
            }
            #pragma unroll
            for (int ni = 0; ni < 2; ni++) {
                int boff = (nh * 32 + ni * 16) * LDT + ks * 16;
                wmma::load_matrix_sync(fbh[ni], Bh + boff, LDT);
                wmma::load_matrix_sync(fbl[ni], Bl + boff, LDT);
            }
            #pragma unroll
            for (int mi = 0; mi < 2; mi++)
                #pragma unroll
                for (int ni = 0; ni < 2; ni++) {
                    wmma::mma_sync(acc[mi][ni], fah[mi], fbh[ni], acc[mi][ni]);
                    wmma::mma_sync(acc[mi][ni], fah[mi], fbl[ni], acc[mi][ni]);
                    wmma::mma_sync(acc[mi][ni], fal[mi], fbh[ni], acc[mi][ni]);
                }
        }
        __syncthreads();                         // all reads done before refill
    }

    // ---- store k-partials into smem (alias dead buffers) ----
    {
        float* P = (float*)(smem + OFF_P(kq));
        #pragma unroll
        for (int mi = 0; mi < 2; mi++)
            #pragma unroll
            for (int ni = 0; ni < 2; ni++)
                wmma::store_matrix_sync(P + (mh * 32 + mi * 16) * 72 + nh * 32 + ni * 16,
                                        acc[mi][ni], 72, wmma::mem_row_major);
    }
    __syncthreads();

    // ---- fused k-reduce + bf16 hi/lo split (512 threads) ----
    {
        const float* P1 = (const float*)(smem + OFF_P(1));
        const float* P2 = (const float*)(smem + OFF_P(2));
        const float* P3 = (const float*)(smem + OFF_P(3));
        #pragma unroll
        for (int i = 0; i < 8; i++) {
            int idx = tid + i * NTHR;              // 4096
            int row = idx >> 6, col = idx & 63;
            int e = row * 72 + col;
            float v = hd[e] + P1[e] + P2[e] + P3[e];
            hd[e] = v;                              // in place (P0)
            __nv_bfloat16 hi = __float2bfloat16(v);
            hdh[e] = hi;
            hdl[e] = __float2bfloat16(v - __bfloat162float(hi));
        }
    }
    __syncthreads();

    // ---- gates GEMM: gd[192 x 64] = W_hh · h_diff; 48 tiles, 3 per warp ----
    {
        #pragma unroll
        for (int i = 0; i < 3; i++) {
            int tile = wid * 3 + i;                // 0..47
            int gm = tile >> 2, gn = tile & 3;     // 12 x 4
            wmma::fragment<wmma::accumulator, 16, 16, 16, float> gacc;
            wmma::fill_fragment(gacc, 0.f);
            #pragma unroll
            for (int ks = 0; ks < 4; ks++) {
                wmma::fragment<wmma::matrix_a, 16, 16, 16, __nv_bfloat16, wmma::row_major> fah, fal;
                wmma::fragment<wmma::matrix_b, 16, 16, 16, __nv_bfloat16, wmma::row_major> gbh, gbl;
                int aoff = gm * 16 * 64 + ks * 16;
                int boff = ks * 16 * 72 + gn * 16;
                wmma::load_matrix_sync(fah, g_whh_h + aoff, 64);
                wmma::load_matrix_sync(fal, g_whh_l + aoff, 64);
                wmma::load_matrix_sync(gbh, hdh + boff, 72);
                wmma::load_matrix_sync(gbl, hdl + boff, 72);
                wmma::mma_sync(gacc, fah, gbh, gacc);
                wmma::mma_sync(gacc, fah, gbl, gacc);
                wmma::mma_sync(gacc, fal, gbh, gacc);
            }
            wmma::store_matrix_sync(gd + gm * 16 * 72 + gn * 16, gacc, 72,
                                    wmma::mem_row_major);
        }
    }
    __syncthreads();

    // ---- nonlinearity + state update: thread = (q 0..7, w 0..63), 8 hh ----
    {
        const int w = tid & 63;
        const int q = tid >> 6;
        float xgv = xg[w];
        #pragma unroll
        for (int k = 0; k < 8; k++) {
            int hh = q + 8 * k;
            float ar = gd[hh * 72 + w];
            float az = gd[(64 + hh) * 72 + w];
            float an = gd[(128 + hh) * 72 + w];
            float r = 0.5f + 0.5f * tanh_fast(0.5f * (ar + gw[hh] * xgv + gw[192 + hh]));
            float z = 0.5f + 0.5f * tanh_fast(0.5f * (az + gw[64 + hh] * xgv + gw[256 + hh]));
            float n = tanh_fast(gw[128 + hh] * xgv + gw[320 + hh] + r * (an + gw[384 + hh]));
            float hd_self = hd[hh * 72 + w];
            float hnew = (1.f - z) * n + z * hd_self;
            size_t si = (size_t)(m0 + hh) * NV + w0 + w;
            __nv_bfloat16 hi = __float2bfloat16(hnew);
            g_hh[nxt][si] = hi;
            g_hl[nxt][si] = __float2bfloat16(hnew - __bfloat162float(hi));
            g_reprs[(size_t)t * BHW + si] = hnew;     // coalesced 128B lines
            hn[hh * 72 + w] = hnew;
        }
    }
    __syncthreads();

    // ---- fused epilogue: imps(t), preds(t+1), g_xh(t+1) ----
    {
        int w = tid & 63, q = tid >> 6;            // q: 8 hid each
        float so = 0.f, si = 0.f;
        #pragma unroll
        for (int j = 0; j < 8; j++) {
            int hh = q * 8 + j;
            float hv = hn[hh * 72 + w];
            so += W_out[hh]  * hv;
            si += W_init[hh] * hv;
        }
        part[q * 64 + w]       = so;
        part[512 + q * 64 + w] = si;
    }
    __syncthreads();
    if (tid < 64) {
        int w = tid;
        float so = 0.f, si = 0.f;
        #pragma unroll
        for (int q = 0; q < 8; q++) {
            so += part[q * 64 + w];
            si += part[512 + q * 64 + w];
        }
        stcs(&out_imps[(b * NV + w0 + w) * NT + t], so + b_out[0]);
        if (t < NT - 1) {
            float d = si + b_init[0];
            int xi = (b * NV + w0 + w) * NT + (t + 1);
            g_xh[b][w0 + w] = (smk[w] != 0.f) ? sx[w] : d;
            stcs(&out_preds[xi], d);
        }
    }
}

// ---------------------------------------------------------------------------
extern "C" void kernel_launch(void* const* d_in, const int* in_sizes, int n_in,
                              void* d_out, int out_size) {
    const float* x          = (const float*)d_in[0];
    const unsigned char* mk = (const unsigned char*)d_in[1];
    const float* graph      = (const float*)d_in[2];
    const float* ind_graph  = (const float*)d_in[3];
    const float* h0         = (const float*)d_in[4];
    const float* W_init     = (const float*)d_in[5];
    const float* b_init     = (const float*)d_in[6];
    const float* W_out      = (const float*)d_in[7];
    const float* b_out      = (const float*)d_in[8];
    const float* W_ih       = (const float*)d_in[9];
    const float* W_hh       = (const float*)d_in[10];
    const float* b_ih       = (const float*)d_in[11];
    const float* b_hh       = (const float*)d_in[12];

    float* out_imps  = (float*)d_out;
    float* out_preds = out_imps + BSZ * NV * NT;
    float* out_reprs = out_preds + BSZ * NV * NT;

    cudaFuncSetAttribute(step_tc_kernel, cudaFuncAttributeMaxDynamicSharedMemorySize,
                         SMEM_TOTAL);

    detect_mask_kernel<<<1, 256>>>((const unsigned int*)mk);
    setup_kernel<<<NV * NV / 256, 256>>>(graph, W_hh, h0);
    prep_kernel<<<dim3(4, BSZ), 256>>>(x, mk, h0, W_init, b_init, out_preds);
    for (int t = 0; t < NT; t++) {
        step_tc_kernel<<<dim3(16, BSZ), NTHR, SMEM_TOTAL>>>(
            t, t & 1, x, mk, ind_graph,
            W_init, b_init, W_out, b_out, W_ih, b_ih, b_hh,
            out_imps, out_preds);
    }
    transpose_reprs_kernel<<<BHW / 64, 256>>>(out_reprs);
}